// round 10
// baseline (speedup 1.0000x reference)
#include <cuda_runtime.h>
#include <cuda_bf16.h>

// ---------------- Problem constants ----------------
#define KBOX   1024
#define ROWS_I 1023
#define TM     128
#define NTILES 8184                  // 1,047,552 / 128
#define NTHREADS 512
#define GRID   148                   // persistent, 1 CTA per SM

// bf16 tile row stride: 136 elems = 272 bytes (mod 128 = 16 -> ldmatrix conflict-free)
#define SROW_B 272

// ---------------- smem layout (bytes) ----------------
#define OFF_W2HI 0                       // [128 k][136] bf16 = 34816
#define OFF_W2LO 34816
#define OFF_HHI  69632                   // [128 m][136] bf16
#define OFF_HLO  104448
#define OFF_FT   139264                  // [13][128] f32 = 6656
#define OFF_W1   145920                  // [13][128] f32 = 6656
#define OFF_B2   152576                  // [128] f32 = 512
#define SMEM_BYTES 153088

// Packed dual fp32 FMA (ptxas never auto-fuses)
__device__ __forceinline__ float2 ffma2(float2 a, float2 b, float2 c) {
    float2 d;
    asm("fma.rn.f32x2 %0, %1, %2, %3;"
        : "=l"(*reinterpret_cast<unsigned long long*>(&d))
        : "l"(*reinterpret_cast<unsigned long long*>(&a)),
          "l"(*reinterpret_cast<unsigned long long*>(&b)),
          "l"(*reinterpret_cast<unsigned long long*>(&c)));
    return d;
}
__device__ __forceinline__ float2 splat2(float v) { return make_float2(v, v); }

__device__ __forceinline__ unsigned smem_u32(const void* p) {
    unsigned a;
    asm("{ .reg .u64 t; cvta.to.shared.u64 t, %1; cvt.u32.u64 %0, t; }" : "=r"(a) : "l"(p));
    return a;
}

__device__ __forceinline__ void ldsm4(unsigned* r, unsigned addr) {
    asm volatile("ldmatrix.sync.aligned.m8n8.x4.shared.b16 {%0,%1,%2,%3}, [%4];"
                 : "=r"(r[0]), "=r"(r[1]), "=r"(r[2]), "=r"(r[3]) : "r"(addr));
}
__device__ __forceinline__ void ldsm4t(unsigned* r, unsigned addr) {
    asm volatile("ldmatrix.sync.aligned.m8n8.x4.trans.shared.b16 {%0,%1,%2,%3}, [%4];"
                 : "=r"(r[0]), "=r"(r[1]), "=r"(r[2]), "=r"(r[3]) : "r"(addr));
}
__device__ __forceinline__ void mma_bf16(float* c, const unsigned* a, unsigned b0, unsigned b1) {
    asm volatile("mma.sync.aligned.m16n8k16.row.col.f32.bf16.bf16.f32 "
                 "{%0,%1,%2,%3}, {%4,%5,%6,%7}, {%8,%9}, {%0,%1,%2,%3};"
                 : "+f"(c[0]), "+f"(c[1]), "+f"(c[2]), "+f"(c[3])
                 : "r"(a[0]), "r"(a[1]), "r"(a[2]), "r"(a[3]), "r"(b0), "r"(b1));
}

__device__ __forceinline__ void split1(float v, unsigned short& h, unsigned short& l) {
    __nv_bfloat16 hb = __float2bfloat16_rn(v);
    __nv_bfloat16 lb = __float2bfloat16_rn(v - __bfloat162float(hb));
    h = __bfloat16_as_ushort(hb);
    l = __bfloat16_as_ushort(lb);
}

// Pair features for global row r -> column col of sFT
__device__ __forceinline__ void feats_row(const float4* __restrict__ boxes4,
                                          int r, int col, float* __restrict__ sFT)
{
    const int i = r / ROWS_I;
    const int p = r - i * ROWS_I;
    const int j = (p < i) ? p : p + 1;

    const float4 bi = boxes4[i];
    const float4 bj = boxes4[j];
    const float xi = bi.x, yi = bi.y, wi = bi.z, hi = bi.w;
    const float xj = bj.x, yj = bj.y, wj = bj.z, hj = bj.w;

    const float dx = __fdividef(xj - xi, wi);
    const float dy = __fdividef(yj - yi, hi);
    const float dw = __logf(__fdividef(wj, wi) + 1e-6f);
    const float dh = __logf(__fdividef(hj, hi) + 1e-6f);
    const float iw = fmaxf(0.0f, fminf(xi + wi, xj + wj) - fmaxf(xi, xj));
    const float ih = fmaxf(0.0f, fminf(yi + hi, yj + hj) - fmaxf(yi, yj));
    const float inter = iw * ih;
    const float uni = wi * hi + wj * hj - inter;
    const float iou = __fdividef(inter, uni + 1e-6f);

    sFT[0*TM + col] = dx;  sFT[1*TM + col] = dy;  sFT[2*TM + col] = dw;
    sFT[3*TM + col] = dh;  sFT[4*TM + col] = wi;  sFT[5*TM + col] = hi;
    sFT[6*TM + col] = wj;  sFT[7*TM + col] = hj;  sFT[8*TM + col] = iou;
    sFT[9*TM + col] = xi;  sFT[10*TM + col] = yi; sFT[11*TM + col] = xj;
    sFT[12*TM + col] = yj;
}

__global__ void __launch_bounds__(NTHREADS, 1)
pair_mlp_kernel(const float* __restrict__ boxes,
                const float* __restrict__ W1,
                const float* __restrict__ b1,
                const float* __restrict__ W2,
                const float* __restrict__ b2,
                float* __restrict__ out)
{
    extern __shared__ __align__(16) char smem[];
    const unsigned sbase = smem_u32(smem);
    float* sFT = (float*)(smem + OFF_FT);
    float* sW1 = (float*)(smem + OFF_W1);
    float* sB2 = (float*)(smem + OFF_B2);

    const int t   = threadIdx.x;
    const int lid = t & 31;
    const int wid = t >> 5;            // 0..15
    const float4* boxes4 = reinterpret_cast<const float4*>(boxes);

    // ---- one-time staging ----
    // W2 split -> bf16 hi/lo tiles [k][n], stride 272B
    for (int idx = t; idx < 128 * 128; idx += NTHREADS) {
        const int k = idx >> 7, n = idx & 127;
        unsigned short h, l;
        split1(W2[idx], h, l);
        *(unsigned short*)(smem + OFF_W2HI + k * SROW_B + n * 2) = h;
        *(unsigned short*)(smem + OFF_W2LO + k * SROW_B + n * 2) = l;
    }
    for (int i = t; i < 13 * 128; i += NTHREADS) sW1[i] = W1[i];
    if (t < 128) sB2[t] = b2[t];

    // GEMM1 bias (lane covers hidden cols 4*lid..4*lid+3)
    const float4 b1v = *reinterpret_cast<const float4*>(b1 + 4 * lid);

    // phase B warp tile: 4x4 warp grid, each warp 32 rows x 32 cols
    const int m0w = (wid & 3) * 32;
    const int n0w = (wid >> 2) * 32;
    // k-stagger: same-SMSP warps (same wid&3, different wid>>2) start at
    // different ksteps so ldsm bursts and mma bursts overlap across warps.
    const int kstart = (wid >> 2) * 2;

    // feats for first tile
    if (t < TM) feats_row(boxes4, blockIdx.x * TM + t, t, sFT);
    __syncthreads();

    for (int tile = blockIdx.x; tile < NTILES; tile += GRID) {
        // ============ Phase A: GEMM1 + relu + bf16 split -> sH tiles ============
        // warp -> 8 m rows, lane -> hidden cols 4*lid..4*lid+3 (contiguous STS)
        {
            float4 w1r[13];
            #pragma unroll
            for (int kk = 0; kk < 13; kk++)
                w1r[kk] = *reinterpret_cast<const float4*>(&sW1[kk * 128 + 4 * lid]);

            #pragma unroll 4
            for (int m = 0; m < 8; m++) {
                const int row = wid * 8 + m;
                float2 a01 = make_float2(b1v.x, b1v.y);
                float2 a23 = make_float2(b1v.z, b1v.w);
                #pragma unroll
                for (int kk = 0; kk < 13; kk++) {
                    const float2 f2 = splat2(sFT[kk * TM + row]);   // warp broadcast
                    a01 = ffma2(f2, make_float2(w1r[kk].x, w1r[kk].y), a01);
                    a23 = ffma2(f2, make_float2(w1r[kk].z, w1r[kk].w), a23);
                }
                const float v0 = fmaxf(a01.x, 0.f), v1 = fmaxf(a01.y, 0.f);
                const float v2 = fmaxf(a23.x, 0.f), v3 = fmaxf(a23.y, 0.f);
                unsigned short h0, l0, h1, l1, h2, l2, h3, l3;
                split1(v0, h0, l0); split1(v1, h1, l1);
                split1(v2, h2, l2); split1(v3, h3, l3);
                const unsigned ro = (unsigned)(row * SROW_B + 8 * lid);
                *(uint2*)(smem + OFF_HHI + ro) =
                    make_uint2((unsigned)h0 | ((unsigned)h1 << 16),
                               (unsigned)h2 | ((unsigned)h3 << 16));
                *(uint2*)(smem + OFF_HLO + ro) =
                    make_uint2((unsigned)l0 | ((unsigned)l1 << 16),
                               (unsigned)l2 | ((unsigned)l3 << 16));
            }
        }
        __syncthreads();

        // ============ Phase B: GEMM2 via bf16 mma.sync (hi/lo split, 3 passes) ============
        float acc[2][4][4];
        #pragma unroll
        for (int mt = 0; mt < 2; mt++)
            #pragma unroll
            for (int nt = 0; nt < 4; nt++)
                #pragma unroll
                for (int q = 0; q < 4; q++) acc[mt][nt][q] = 0.0f;

        const unsigned arow = (unsigned)((m0w + (lid & 15)) * SROW_B + ((lid >> 4) << 4));
        const unsigned brow = (unsigned)((lid & 15) * SROW_B + (n0w + ((lid >> 4) << 3)) * 2);

        #pragma unroll
        for (int ki = 0; ki < 8; ki++) {
            const unsigned ks = (unsigned)((ki + kstart) & 7);
            const unsigned k0 = ks << 4;
            unsigned ahi[2][4], alo[2][4], bhi[2][4], blo[2][4];

            const unsigned aaddr = sbase + OFF_HHI + arow + k0 * 2;
            ldsm4(ahi[0], aaddr);
            ldsm4(ahi[1], aaddr + 16u * SROW_B);
            ldsm4(alo[0], aaddr + (OFF_HLO - OFF_HHI));
            ldsm4(alo[1], aaddr + (OFF_HLO - OFF_HHI) + 16u * SROW_B);

            const unsigned baddr = sbase + OFF_W2HI + brow + k0 * SROW_B;
            #pragma unroll
            for (int g = 0; g < 2; g++) {
                ldsm4t(bhi[g], baddr + g * 32u);
                ldsm4t(blo[g], baddr + g * 32u + (OFF_W2LO - OFF_W2HI));
            }

            // pass-major issue order: 8 independent mma per pass; any accumulator
            // is reused only after 7 intervening mma -> no dependent back-to-back.
            #pragma unroll
            for (int mt = 0; mt < 2; mt++)
                #pragma unroll
                for (int nt = 0; nt < 4; nt++)
                    mma_bf16(acc[mt][nt], ahi[mt],
                             bhi[nt >> 1][(nt & 1) * 2], bhi[nt >> 1][(nt & 1) * 2 + 1]);
            #pragma unroll
            for (int mt = 0; mt < 2; mt++)
                #pragma unroll
                for (int nt = 0; nt < 4; nt++)
                    mma_bf16(acc[mt][nt], ahi[mt],
                             blo[nt >> 1][(nt & 1) * 2], blo[nt >> 1][(nt & 1) * 2 + 1]);
            #pragma unroll
            for (int mt = 0; mt < 2; mt++)
                #pragma unroll
                for (int nt = 0; nt < 4; nt++)
                    mma_bf16(acc[mt][nt], alo[mt],
                             bhi[nt >> 1][(nt & 1) * 2], bhi[nt >> 1][(nt & 1) * 2 + 1]);
        }

        // ---- epilogue: +b2, direct STG.64 (lane quads -> full 32B sectors) ----
        {
            const size_t rbase = (size_t)tile * TM + m0w + (lid >> 2);
            #pragma unroll
            for (int mt = 0; mt < 2; mt++) {
                const size_t r1 = rbase + mt * 16;
                #pragma unroll
                for (int nt = 0; nt < 4; nt++) {
                    const int cc = n0w + nt * 8 + 2 * (lid & 3);
                    const float2 bb = *reinterpret_cast<const float2*>(&sB2[cc]);
                    float2 o0, o1;
                    o0.x = acc[mt][nt][0] + bb.x; o0.y = acc[mt][nt][1] + bb.y;
                    o1.x = acc[mt][nt][2] + bb.x; o1.y = acc[mt][nt][3] + bb.y;
                    *reinterpret_cast<float2*>(out + r1 * 128 + cc)       = o0;
                    *reinterpret_cast<float2*>(out + (r1 + 8) * 128 + cc) = o1;
                }
            }
        }

        // ---- feats for next tile (sFT free during/after phase B) ----
        const int next = tile + GRID;
        if (next < NTILES && t < TM) feats_row(boxes4, next * TM + t, t, sFT);
        __syncthreads();
    }
}

extern "C" void kernel_launch(void* const* d_in, const int* in_sizes, int n_in,
                              void* d_out, int out_size)
{
    const float* boxes = (const float*)d_in[0];
    const float* W1    = (const float*)d_in[1];
    const float* b1    = (const float*)d_in[2];
    const float* W2    = (const float*)d_in[3];
    const float* b2    = (const float*)d_in[4];
    float* out = (float*)d_out;

    cudaFuncSetAttribute(pair_mlp_kernel,
                         cudaFuncAttributeMaxDynamicSharedMemorySize, SMEM_BYTES);

    pair_mlp_kernel<<<GRID, NTHREADS, SMEM_BYTES>>>(boxes, W1, b1, W2, b2, out);
}

// round 11
// speedup vs baseline: 1.3201x; 1.3201x over previous
#include <cuda_runtime.h>
#include <cuda_bf16.h>

// ---------------- Problem constants ----------------
#define KBOX   1024
#define ROWS_I 1023
#define TM     128
#define NTILES 8184                  // 1,047,552 / 128
#define NTHREADS 512
#define GRID   148                   // persistent, 1 CTA per SM

// bf16 tile row stride: 136 elems = 272 bytes (mod 128 = 16 -> ldmatrix conflict-free)
#define SROW_B 272
#define H_TILE 34816                 // 128 * 272

// ---------------- smem layout (bytes) ----------------
#define OFF_W2HI 0                       // [128 k][136] bf16
#define OFF_W2LO 34816
#define OFF_H    69632                   // 2 bufs x (hi,lo) tiles = 4 x 34816
#define OFF_FT   208896                  // 2 x [13][128] f32 = 2 x 6656
#define SMEM_BYTES 222208

// Packed dual fp32 FMA (ptxas never auto-fuses)
__device__ __forceinline__ float2 ffma2(float2 a, float2 b, float2 c) {
    float2 d;
    asm("fma.rn.f32x2 %0, %1, %2, %3;"
        : "=l"(*reinterpret_cast<unsigned long long*>(&d))
        : "l"(*reinterpret_cast<unsigned long long*>(&a)),
          "l"(*reinterpret_cast<unsigned long long*>(&b)),
          "l"(*reinterpret_cast<unsigned long long*>(&c)));
    return d;
}
__device__ __forceinline__ float2 splat2(float v) { return make_float2(v, v); }

__device__ __forceinline__ unsigned smem_u32(const void* p) {
    unsigned a;
    asm("{ .reg .u64 t; cvta.to.shared.u64 t, %1; cvt.u32.u64 %0, t; }" : "=r"(a) : "l"(p));
    return a;
}

__device__ __forceinline__ void ldsm4(unsigned* r, unsigned addr) {
    asm volatile("ldmatrix.sync.aligned.m8n8.x4.shared.b16 {%0,%1,%2,%3}, [%4];"
                 : "=r"(r[0]), "=r"(r[1]), "=r"(r[2]), "=r"(r[3]) : "r"(addr));
}
__device__ __forceinline__ void ldsm4t(unsigned* r, unsigned addr) {
    asm volatile("ldmatrix.sync.aligned.m8n8.x4.trans.shared.b16 {%0,%1,%2,%3}, [%4];"
                 : "=r"(r[0]), "=r"(r[1]), "=r"(r[2]), "=r"(r[3]) : "r"(addr));
}
__device__ __forceinline__ void mma_bf16(float* c, const unsigned* a, unsigned b0, unsigned b1) {
    asm volatile("mma.sync.aligned.m16n8k16.row.col.f32.bf16.bf16.f32 "
                 "{%0,%1,%2,%3}, {%4,%5,%6,%7}, {%8,%9}, {%0,%1,%2,%3};"
                 : "+f"(c[0]), "+f"(c[1]), "+f"(c[2]), "+f"(c[3])
                 : "r"(a[0]), "r"(a[1]), "r"(a[2]), "r"(a[3]), "r"(b0), "r"(b1));
}

__device__ __forceinline__ void split1(float v, unsigned short& h, unsigned short& l) {
    __nv_bfloat16 hb = __float2bfloat16_rn(v);
    __nv_bfloat16 lb = __float2bfloat16_rn(v - __bfloat162float(hb));
    h = __bfloat16_as_ushort(hb);
    l = __bfloat16_as_ushort(lb);
}

// Pair features for global row r -> column col of sFT
__device__ __forceinline__ void feats_row(const float4* __restrict__ boxes4,
                                          int r, int col, float* __restrict__ sFT)
{
    const int i = r / ROWS_I;
    const int p = r - i * ROWS_I;
    const int j = (p < i) ? p : p + 1;

    const float4 bi = boxes4[i];
    const float4 bj = boxes4[j];
    const float xi = bi.x, yi = bi.y, wi = bi.z, hi = bi.w;
    const float xj = bj.x, yj = bj.y, wj = bj.z, hj = bj.w;

    const float dx = __fdividef(xj - xi, wi);
    const float dy = __fdividef(yj - yi, hi);
    const float dw = __logf(__fdividef(wj, wi) + 1e-6f);
    const float dh = __logf(__fdividef(hj, hi) + 1e-6f);
    const float iw = fmaxf(0.0f, fminf(xi + wi, xj + wj) - fmaxf(xi, xj));
    const float ih = fmaxf(0.0f, fminf(yi + hi, yj + hj) - fmaxf(yi, yj));
    const float inter = iw * ih;
    const float uni = wi * hi + wj * hj - inter;
    const float iou = __fdividef(inter, uni + 1e-6f);

    sFT[0*TM + col] = dx;  sFT[1*TM + col] = dy;  sFT[2*TM + col] = dw;
    sFT[3*TM + col] = dh;  sFT[4*TM + col] = wi;  sFT[5*TM + col] = hi;
    sFT[6*TM + col] = wj;  sFT[7*TM + col] = hj;  sFT[8*TM + col] = iou;
    sFT[9*TM + col] = xi;  sFT[10*TM + col] = yi; sFT[11*TM + col] = xj;
    sFT[12*TM + col] = yj;
}

__global__ void __launch_bounds__(NTHREADS, 1)
pair_mlp_kernel(const float* __restrict__ boxes,
                const float* __restrict__ W1,
                const float* __restrict__ b1,
                const float* __restrict__ W2,
                const float* __restrict__ b2,
                float* __restrict__ out)
{
    extern __shared__ __align__(16) char smem[];
    const unsigned sbase = smem_u32(smem);

    const int t   = threadIdx.x;
    const int lid = t & 31;
    const int wid = t >> 5;            // 0..15
    const float4* boxes4 = reinterpret_cast<const float4*>(boxes);

    float* sFT0 = (float*)(smem + OFF_FT);
    float* sFT1 = (float*)(smem + OFF_FT + 6656);

    // ---- one-time staging: W2 split -> bf16 hi/lo tiles [k][n], stride 272B ----
    for (int idx = t; idx < 128 * 128; idx += NTHREADS) {
        const int k = idx >> 7, n = idx & 127;
        unsigned short h, l;
        split1(W2[idx], h, l);
        *(unsigned short*)(smem + OFF_W2HI + k * SROW_B + n * 2) = h;
        *(unsigned short*)(smem + OFF_W2LO + k * SROW_B + n * 2) = l;
    }

    // ---- register-resident weights/biases ----
    // GEMM1: lane covers hidden cols cbase, cbase+1
    const int cbase = 2 * lid + ((wid >> 3) << 6);
    float2 w1r[13];
    #pragma unroll
    for (int kk = 0; kk < 13; kk++)
        w1r[kk] = *reinterpret_cast<const float2*>(W1 + kk * 128 + cbase);
    const float2 b1p = *reinterpret_cast<const float2*>(b1 + cbase);

    // GEMM2 warp tile: 4x4 warp grid, 32 rows x 32 cols
    const int m0w = (wid & 3) * 32;
    const int n0w = (wid >> 2) * 32;
    float2 b2p[4];
    #pragma unroll
    for (int nt = 0; nt < 4; nt++)
        b2p[nt] = *reinterpret_cast<const float2*>(b2 + n0w + nt * 8 + 2 * (lid & 3));

    // GEMM1 row block for this warp
    const int rb = (wid & 7) * 16;
    const unsigned g1_colb = (unsigned)(4 * lid + ((wid >> 3) << 7)); // byte col offset

    // GEMM2 fragment row offsets (identical to proven R9 layout)
    const unsigned arow = (unsigned)((m0w + (lid & 15)) * SROW_B + ((lid >> 4) << 4));
    const unsigned brow = (unsigned)((lid & 15) * SROW_B + (n0w + ((lid >> 4) << 3)) * 2);

    const int t0 = blockIdx.x;

    // ---- prologue: feats(t0) -> sFT0 ----
    if (t < TM) feats_row(boxes4, t0 * TM + t, t, sFT0);
    __syncthreads();

    // ---- prologue: build H(t0) into buf0; feats(t0+G) -> sFT1 ----
    #pragma unroll
    for (int ki = 0; ki < 8; ki++) {
        const int r0 = rb + 2 * ki;
        float2 a0 = b1p, a1 = b1p;
        #pragma unroll
        for (int kk = 0; kk < 13; kk++) {
            const float2 fp = *reinterpret_cast<const float2*>(&sFT0[kk * TM + r0]);
            a0 = ffma2(splat2(fp.x), w1r[kk], a0);
            a1 = ffma2(splat2(fp.y), w1r[kk], a1);
        }
        a0.x = fmaxf(a0.x, 0.f); a0.y = fmaxf(a0.y, 0.f);
        a1.x = fmaxf(a1.x, 0.f); a1.y = fmaxf(a1.y, 0.f);
        unsigned short h00, l00, h01, l01, h10, l10, h11, l11;
        split1(a0.x, h00, l00); split1(a0.y, h01, l01);
        split1(a1.x, h10, l10); split1(a1.y, h11, l11);
        char* hb = smem + OFF_H + (unsigned)(r0 * SROW_B) + g1_colb;
        *(unsigned*)(hb)                     = (unsigned)h00 | ((unsigned)h01 << 16);
        *(unsigned*)(hb + SROW_B)            = (unsigned)h10 | ((unsigned)h11 << 16);
        *(unsigned*)(hb + H_TILE)            = (unsigned)l00 | ((unsigned)l01 << 16);
        *(unsigned*)(hb + H_TILE + SROW_B)   = (unsigned)l10 | ((unsigned)l11 << 16);
    }
    if (t0 + GRID < NTILES && wid < 8 && lid < 16)
        feats_row(boxes4, (t0 + GRID) * TM + rb + lid, rb + lid, sFT1);
    __syncthreads();

    int hcur = 0, fcur = 1;

    // ---- main pipelined loop ----
    for (int tile = t0; tile < NTILES; tile += GRID) {
        const int nH = tile + GRID;
        const int nF = tile + 2 * GRID;
        const bool doG1 = (nH < NTILES);

        // feats two tiles ahead into the other sFT buffer
        if (nF < NTILES && wid < 8 && lid < 16)
            feats_row(boxes4, nF * TM + rb + lid, rb + lid,
                      (fcur ? sFT0 : sFT1));

        const float* sF = fcur ? sFT1 : sFT0;
        const unsigned hbase = OFF_H + (unsigned)hcur * (2u * H_TILE);
        const unsigned hnextb = OFF_H + (unsigned)(hcur ^ 1) * (2u * H_TILE);

        float acc[2][4][4];
        #pragma unroll
        for (int mt = 0; mt < 2; mt++)
            #pragma unroll
            for (int nt = 0; nt < 4; nt++)
                #pragma unroll
                for (int q = 0; q < 4; q++) acc[mt][nt][q] = 0.0f;

        #pragma unroll
        for (int ki = 0; ki < 8; ki++) {
            const unsigned k0 = (unsigned)ki << 4;
            unsigned ahi[2][4], alo[2][4], bhi[2][4], blo[2][4];

            const unsigned aaddr = sbase + hbase + arow + k0 * 2;
            ldsm4(ahi[0], aaddr);
            ldsm4(ahi[1], aaddr + 16u * SROW_B);
            ldsm4(alo[0], aaddr + H_TILE);
            ldsm4(alo[1], aaddr + H_TILE + 16u * SROW_B);

            const unsigned baddr = sbase + OFF_W2HI + brow + k0 * SROW_B;
            #pragma unroll
            for (int g = 0; g < 2; g++) {
                ldsm4t(bhi[g], baddr + g * 32u);
                ldsm4t(blo[g], baddr + g * 32u + (OFF_W2LO - OFF_W2HI));
            }

            #pragma unroll
            for (int mt = 0; mt < 2; mt++) {
                #pragma unroll
                for (int nt = 0; nt < 4; nt++) {
                    const unsigned bh0 = bhi[nt >> 1][(nt & 1) * 2];
                    const unsigned bh1 = bhi[nt >> 1][(nt & 1) * 2 + 1];
                    const unsigned bl0 = blo[nt >> 1][(nt & 1) * 2];
                    const unsigned bl1 = blo[nt >> 1][(nt & 1) * 2 + 1];
                    mma_bf16(acc[mt][nt], ahi[mt], bh0, bh1);
                    mma_bf16(acc[mt][nt], ahi[mt], bl0, bl1);
                    mma_bf16(acc[mt][nt], alo[mt], bh0, bh1);
                }
            }

            // ---- interleaved GEMM1 chunk for next tile: 2 rows x 2 cols ----
            if (doG1) {
                const int r0 = rb + 2 * ki;
                float2 a0 = b1p, a1 = b1p;
                #pragma unroll
                for (int kk = 0; kk < 13; kk++) {
                    const float2 fp = *reinterpret_cast<const float2*>(&sF[kk * TM + r0]);
                    a0 = ffma2(splat2(fp.x), w1r[kk], a0);
                    a1 = ffma2(splat2(fp.y), w1r[kk], a1);
                }
                a0.x = fmaxf(a0.x, 0.f); a0.y = fmaxf(a0.y, 0.f);
                a1.x = fmaxf(a1.x, 0.f); a1.y = fmaxf(a1.y, 0.f);
                unsigned short h00, l00, h01, l01, h10, l10, h11, l11;
                split1(a0.x, h00, l00); split1(a0.y, h01, l01);
                split1(a1.x, h10, l10); split1(a1.y, h11, l11);
                char* hb = smem + hnextb + (unsigned)(r0 * SROW_B) + g1_colb;
                *(unsigned*)(hb)                   = (unsigned)h00 | ((unsigned)h01 << 16);
                *(unsigned*)(hb + SROW_B)          = (unsigned)h10 | ((unsigned)h11 << 16);
                *(unsigned*)(hb + H_TILE)          = (unsigned)l00 | ((unsigned)l01 << 16);
                *(unsigned*)(hb + H_TILE + SROW_B) = (unsigned)l10 | ((unsigned)l11 << 16);
            }
        }

        // ---- epilogue: +b2, direct STG.64 (lane quads -> full 32B sectors) ----
        {
            const size_t rbase = (size_t)tile * TM + m0w + (lid >> 2);
            #pragma unroll
            for (int mt = 0; mt < 2; mt++) {
                const size_t r1 = rbase + mt * 16;
                #pragma unroll
                for (int nt = 0; nt < 4; nt++) {
                    const int cc = n0w + nt * 8 + 2 * (lid & 3);
                    float2 o0, o1;
                    o0.x = acc[mt][nt][0] + b2p[nt].x; o0.y = acc[mt][nt][1] + b2p[nt].y;
                    o1.x = acc[mt][nt][2] + b2p[nt].x; o1.y = acc[mt][nt][3] + b2p[nt].y;
                    *reinterpret_cast<float2*>(out + r1 * 128 + cc)       = o0;
                    *reinterpret_cast<float2*>(out + (r1 + 8) * 128 + cc) = o1;
                }
            }
        }

        __syncthreads();
        hcur ^= 1; fcur ^= 1;
    }
}

extern "C" void kernel_launch(void* const* d_in, const int* in_sizes, int n_in,
                              void* d_out, int out_size)
{
    const float* boxes = (const float*)d_in[0];
    const float* W1    = (const float*)d_in[1];
    const float* b1    = (const float*)d_in[2];
    const float* W2    = (const float*)d_in[3];
    const float* b2    = (const float*)d_in[4];
    float* out = (float*)d_out;

    cudaFuncSetAttribute(pair_mlp_kernel,
                         cudaFuncAttributeMaxDynamicSharedMemorySize, SMEM_BYTES);

    pair_mlp_kernel<<<GRID, NTHREADS, SMEM_BYTES>>>(boxes, W1, b1, W2, b2, out);
}

// round 15
// speedup vs baseline: 1.7229x; 1.3051x over previous
#include <cuda_runtime.h>
#include <cuda_fp16.h>

// ---------------- Problem constants ----------------
#define KBOX   1024
#define ROWS_I 1023
#define TM     128
#define NTILES 8184                  // 1,047,552 / 128
#define NTHREADS 512
#define GRID   148                   // persistent, 1 CTA per SM

// fp16 tile row stride: 136 elems = 272 bytes (mod 128 = 16 -> ldmatrix conflict-free)
#define SROW_B 272
#define H_TILE 34816                 // 128 * 272

// ---------------- smem layout (bytes) ----------------
#define OFF_W2HI 0                       // [128 k][136] fp16
#define OFF_W2LO 34816
#define OFF_H    69632                   // 2 bufs x hi-only tile = 2 x 34816
#define OFF_FT   139264                  // 2 x [13][128] f32 = 2 x 6656
#define SMEM_BYTES 152576

// Packed dual fp32 FMA (ptxas never auto-fuses)
__device__ __forceinline__ float2 ffma2(float2 a, float2 b, float2 c) {
    float2 d;
    asm("fma.rn.f32x2 %0, %1, %2, %3;"
        : "=l"(*reinterpret_cast<unsigned long long*>(&d))
        : "l"(*reinterpret_cast<unsigned long long*>(&a)),
          "l"(*reinterpret_cast<unsigned long long*>(&b)),
          "l"(*reinterpret_cast<unsigned long long*>(&c)));
    return d;
}
__device__ __forceinline__ float2 splat2(float v) { return make_float2(v, v); }

__device__ __forceinline__ unsigned smem_u32(const void* p) {
    unsigned a;
    asm("{ .reg .u64 t; cvta.to.shared.u64 t, %1; cvt.u32.u64 %0, t; }" : "=r"(a) : "l"(p));
    return a;
}

__device__ __forceinline__ void ldsm4(unsigned* r, unsigned addr) {
    asm volatile("ldmatrix.sync.aligned.m8n8.x4.shared.b16 {%0,%1,%2,%3}, [%4];"
                 : "=r"(r[0]), "=r"(r[1]), "=r"(r[2]), "=r"(r[3]) : "r"(addr));
}
__device__ __forceinline__ void ldsm4t(unsigned* r, unsigned addr) {
    asm volatile("ldmatrix.sync.aligned.m8n8.x4.trans.shared.b16 {%0,%1,%2,%3}, [%4];"
                 : "=r"(r[0]), "=r"(r[1]), "=r"(r[2]), "=r"(r[3]) : "r"(addr));
}
__device__ __forceinline__ void mma_f16(float* c, const unsigned* a, unsigned b0, unsigned b1) {
    asm volatile("mma.sync.aligned.m16n8k16.row.col.f32.f16.f16.f32 "
                 "{%0,%1,%2,%3}, {%4,%5,%6,%7}, {%8,%9}, {%0,%1,%2,%3};"
                 : "+f"(c[0]), "+f"(c[1]), "+f"(c[2]), "+f"(c[3])
                 : "r"(a[0]), "r"(a[1]), "r"(a[2]), "r"(a[3]), "r"(b0), "r"(b1));
}

// fp16 hi/lo split (for W2)
__device__ __forceinline__ void split1h(float v, unsigned short& h, unsigned short& l) {
    __half hb = __float2half_rn(v);
    __half lb = __float2half_rn(v - __half2float(hb));
    h = __half_as_ushort(hb);
    l = __half_as_ushort(lb);
}

// Pair features for global row r -> column col of sFT
__device__ __forceinline__ void feats_row(const float4* __restrict__ boxes4,
                                          int r, int col, float* __restrict__ sFT)
{
    const int i = r / ROWS_I;
    const int p = r - i * ROWS_I;
    const int j = (p < i) ? p : p + 1;

    const float4 bi = boxes4[i];
    const float4 bj = boxes4[j];
    const float xi = bi.x, yi = bi.y, wi = bi.z, hi = bi.w;
    const float xj = bj.x, yj = bj.y, wj = bj.z, hj = bj.w;

    const float dx = __fdividef(xj - xi, wi);
    const float dy = __fdividef(yj - yi, hi);
    const float dw = __logf(__fdividef(wj, wi) + 1e-6f);
    const float dh = __logf(__fdividef(hj, hi) + 1e-6f);
    const float iw = fmaxf(0.0f, fminf(xi + wi, xj + wj) - fmaxf(xi, xj));
    const float ih = fmaxf(0.0f, fminf(yi + hi, yj + hj) - fmaxf(yi, yj));
    const float inter = iw * ih;
    const float uni = wi * hi + wj * hj - inter;
    const float iou = __fdividef(inter, uni + 1e-6f);

    sFT[0*TM + col] = dx;  sFT[1*TM + col] = dy;  sFT[2*TM + col] = dw;
    sFT[3*TM + col] = dh;  sFT[4*TM + col] = wi;  sFT[5*TM + col] = hi;
    sFT[6*TM + col] = wj;  sFT[7*TM + col] = hj;  sFT[8*TM + col] = iou;
    sFT[9*TM + col] = xi;  sFT[10*TM + col] = yi; sFT[11*TM + col] = xj;
    sFT[12*TM + col] = yj;
}

__global__ void __launch_bounds__(NTHREADS, 1)
pair_mlp_kernel(const float* __restrict__ boxes,
                const float* __restrict__ W1,
                const float* __restrict__ b1,
                const float* __restrict__ W2,
                const float* __restrict__ b2,
                float* __restrict__ out)
{
    extern __shared__ __align__(16) char smem[];
    const unsigned sbase = smem_u32(smem);

    const int t   = threadIdx.x;
    const int lid = t & 31;
    const int wid = t >> 5;            // 0..15
    const float4* boxes4 = reinterpret_cast<const float4*>(boxes);

    float* sFT0 = (float*)(smem + OFF_FT);
    float* sFT1 = (float*)(smem + OFF_FT + 6656);

    // ---- one-time staging: W2 split -> fp16 hi/lo tiles [k][n], stride 272B ----
    for (int idx = t; idx < 128 * 128; idx += NTHREADS) {
        const int k = idx >> 7, n = idx & 127;
        unsigned short h, l;
        split1h(W2[idx], h, l);
        *(unsigned short*)(smem + OFF_W2HI + k * SROW_B + n * 2) = h;
        *(unsigned short*)(smem + OFF_W2LO + k * SROW_B + n * 2) = l;
    }

    // ---- register-resident weights/biases ----
    // GEMM1: lane covers hidden cols cbase, cbase+1
    const int cbase = 2 * lid + ((wid >> 3) << 6);
    float2 w1r[13];
    #pragma unroll
    for (int kk = 0; kk < 13; kk++)
        w1r[kk] = *reinterpret_cast<const float2*>(W1 + kk * 128 + cbase);
    const float2 b1p = *reinterpret_cast<const float2*>(b1 + cbase);

    // GEMM2 warp tile: 4x4 warp grid, 32 rows x 32 cols
    const int m0w = (wid & 3) * 32;
    const int n0w = (wid >> 2) * 32;
    float2 b2p[4];
    #pragma unroll
    for (int nt = 0; nt < 4; nt++)
        b2p[nt] = *reinterpret_cast<const float2*>(b2 + n0w + nt * 8 + 2 * (lid & 3));

    // GEMM1 row block for this warp
    const int rb = (wid & 7) * 16;
    const unsigned g1_colb = (unsigned)(4 * lid + ((wid >> 3) << 7)); // byte col offset

    // GEMM2 fragment row offsets
    const unsigned arow = (unsigned)((m0w + (lid & 15)) * SROW_B + ((lid >> 4) << 4));
    const unsigned brow = (unsigned)((lid & 15) * SROW_B + (n0w + ((lid >> 4) << 3)) * 2);

    const int t0 = blockIdx.x;

    // ---- prologue: feats(t0) -> sFT0 ----
    if (t < TM) feats_row(boxes4, t0 * TM + t, t, sFT0);
    __syncthreads();

    // ---- prologue: build H(t0) (hi only) into buf0; feats(t0+G) -> sFT1 ----
    #pragma unroll
    for (int ki = 0; ki < 8; ki++) {
        const int r0 = rb + 2 * ki;
        float2 a0 = b1p, a1 = b1p;
        #pragma unroll
        for (int kk = 0; kk < 13; kk++) {
            const float2 fp = *reinterpret_cast<const float2*>(&sFT0[kk * TM + r0]);
            a0 = ffma2(splat2(fp.x), w1r[kk], a0);
            a1 = ffma2(splat2(fp.y), w1r[kk], a1);
        }
        const unsigned h00 = __half_as_ushort(__float2half_rn(fmaxf(a0.x, 0.f)));
        const unsigned h01 = __half_as_ushort(__float2half_rn(fmaxf(a0.y, 0.f)));
        const unsigned h10 = __half_as_ushort(__float2half_rn(fmaxf(a1.x, 0.f)));
        const unsigned h11 = __half_as_ushort(__float2half_rn(fmaxf(a1.y, 0.f)));
        char* hb = smem + OFF_H + (unsigned)(r0 * SROW_B) + g1_colb;
        *(unsigned*)(hb)          = h00 | (h01 << 16);
        *(unsigned*)(hb + SROW_B) = h10 | (h11 << 16);
    }
    if (t0 + GRID < NTILES && wid < 8 && lid < 16)
        feats_row(boxes4, (t0 + GRID) * TM + rb + lid, rb + lid, sFT1);
    __syncthreads();

    int hcur = 0, fcur = 1;

    // ---- main pipelined loop ----
    for (int tile = t0; tile < NTILES; tile += GRID) {
        const int nH = tile + GRID;
        const int nF = tile + 2 * GRID;
        const bool doG1 = (nH < NTILES);

        // feats two tiles ahead into the other sFT buffer
        if (nF < NTILES && wid < 8 && lid < 16)
            feats_row(boxes4, nF * TM + rb + lid, rb + lid,
                      (fcur ? sFT0 : sFT1));

        const float* sF = fcur ? sFT1 : sFT0;
        const unsigned hbase  = OFF_H + (unsigned)hcur * H_TILE;
        const unsigned hnextb = OFF_H + (unsigned)(hcur ^ 1) * H_TILE;

        float acc[2][4][4];
        #pragma unroll
        for (int mt = 0; mt < 2; mt++)
            #pragma unroll
            for (int nt = 0; nt < 4; nt++)
                #pragma unroll
                for (int q = 0; q < 4; q++) acc[mt][nt][q] = 0.0f;

        #pragma unroll
        for (int ki = 0; ki < 8; ki++) {
            const unsigned k0 = (unsigned)ki << 4;
            unsigned ahi[2][4], bhi[2][4], blo[2][4];

            const unsigned aaddr = sbase + hbase + arow + k0 * 2;
            ldsm4(ahi[0], aaddr);
            ldsm4(ahi[1], aaddr + 16u * SROW_B);

            const unsigned baddr = sbase + OFF_W2HI + brow + k0 * SROW_B;
            #pragma unroll
            for (int g = 0; g < 2; g++) {
                ldsm4t(bhi[g], baddr + g * 32u);
                ldsm4t(blo[g], baddr + g * 32u + (OFF_W2LO - OFF_W2HI));
            }

            // 2 passes: ahi*bhi + ahi*blo (B captured exactly; only a_lo dropped)
            #pragma unroll
            for (int mt = 0; mt < 2; mt++) {
                #pragma unroll
                for (int nt = 0; nt < 4; nt++) {
                    const unsigned bh0 = bhi[nt >> 1][(nt & 1) * 2];
                    const unsigned bh1 = bhi[nt >> 1][(nt & 1) * 2 + 1];
                    const unsigned bl0 = blo[nt >> 1][(nt & 1) * 2];
                    const unsigned bl1 = blo[nt >> 1][(nt & 1) * 2 + 1];
                    mma_f16(acc[mt][nt], ahi[mt], bh0, bh1);
                    mma_f16(acc[mt][nt], ahi[mt], bl0, bl1);
                }
            }

            // ---- interleaved GEMM1 chunk for next tile: 2 rows x 2 cols (hi only) ----
            if (doG1) {
                const int r0 = rb + 2 * ki;
                float2 a0 = b1p, a1 = b1p;
                #pragma unroll
                for (int kk = 0; kk < 13; kk++) {
                    const float2 fp = *reinterpret_cast<const float2*>(&sF[kk * TM + r0]);
                    a0 = ffma2(splat2(fp.x), w1r[kk], a0);
                    a1 = ffma2(splat2(fp.y), w1r[kk], a1);
                }
                const unsigned h00 = __half_as_ushort(__float2half_rn(fmaxf(a0.x, 0.f)));
                const unsigned h01 = __half_as_ushort(__float2half_rn(fmaxf(a0.y, 0.f)));
                const unsigned h10 = __half_as_ushort(__float2half_rn(fmaxf(a1.x, 0.f)));
                const unsigned h11 = __half_as_ushort(__float2half_rn(fmaxf(a1.y, 0.f)));
                char* hb = smem + hnextb + (unsigned)(r0 * SROW_B) + g1_colb;
                *(unsigned*)(hb)          = h00 | (h01 << 16);
                *(unsigned*)(hb + SROW_B) = h10 | (h11 << 16);
            }
        }

        // ---- epilogue: +b2, direct STG.64 (lane quads -> full 32B sectors) ----
        {
            const size_t rbase = (size_t)tile * TM + m0w + (lid >> 2);
            #pragma unroll
            for (int mt = 0; mt < 2; mt++) {
                const size_t r1 = rbase + mt * 16;
                #pragma unroll
                for (int nt = 0; nt < 4; nt++) {
                    const int cc = n0w + nt * 8 + 2 * (lid & 3);
                    float2 o0, o1;
                    o0.x = acc[mt][nt][0] + b2p[nt].x; o0.y = acc[mt][nt][1] + b2p[nt].y;
                    o1.x = acc[mt][nt][2] + b2p[nt].x; o1.y = acc[mt][nt][3] + b2p[nt].y;
                    *reinterpret_cast<float2*>(out + r1 * 128 + cc)       = o0;
                    *reinterpret_cast<float2*>(out + (r1 + 8) * 128 + cc) = o1;
                }
            }
        }

        __syncthreads();
        hcur ^= 1; fcur ^= 1;
    }
}

extern "C" void kernel_launch(void* const* d_in, const int* in_sizes, int n_in,
                              void* d_out, int out_size)
{
    const float* boxes = (const float*)d_in[0];
    const float* W1    = (const float*)d_in[1];
    const float* b1    = (const float*)d_in[2];
    const float* W2    = (const float*)d_in[3];
    const float* b2    = (const float*)d_in[4];
    float* out = (float*)d_out;

    cudaFuncSetAttribute(pair_mlp_kernel,
                         cudaFuncAttributeMaxDynamicSharedMemorySize, SMEM_BYTES);

    pair_mlp_kernel<<<GRID, NTHREADS, SMEM_BYTES>>>(boxes, W1, b1, W2, b2, out);
}